// round 5
// baseline (speedup 1.0000x reference)
#include <cuda_runtime.h>
#include <cuda_bf16.h>
#include <math.h>
#include <stdint.h>

// NTXentLoss: normalize -> (zj @ zi^T)/T -> per-row masked sum(exp) -> log - pos -> mean
// B=8192, D=128, T=0.1. mma.sync bf16 + cp.async pipelined tiles + MUFU.EX2 epilogue.

#define B_SZ 8192
#define D_SZ 128

__device__ float         g_zi32[B_SZ * D_SZ];
__device__ float         g_zj32[B_SZ * D_SZ];
__device__ __nv_bfloat16 g_zib[B_SZ * D_SZ];
__device__ __nv_bfloat16 g_zjb[B_SZ * D_SZ];
__device__ float         g_pos[B_SZ];
__device__ float         g_part[B_SZ * 16];   // [row][colQuad]
__device__ float         g_blocksum[32];

#define EXP_C1 14.42695040888963f             // 10 * log2(e)

__device__ __forceinline__ float exp10m(float a) {
    float t = a * EXP_C1;
    float r;
    asm("ex2.approx.f32 %0, %1;" : "=f"(r) : "f"(t));
    return r;
}
__device__ __forceinline__ uint32_t smem_u32(const void* p) {
    uint32_t a;
    asm("{ .reg .u64 t; cvta.to.shared.u64 t, %1; cvt.u32.u64 %0, t; }" : "=r"(a) : "l"(p));
    return a;
}
__device__ __forceinline__ void cpasync16(uint32_t dst, const void* src) {
    asm volatile("cp.async.cg.shared.global [%0], [%1], 16;" :: "r"(dst), "l"(src));
}
#define CP_COMMIT() asm volatile("cp.async.commit_group;" ::: "memory")
#define CP_WAIT0()  asm volatile("cp.async.wait_group 0;" ::: "memory")

__device__ __forceinline__ void ldsm4(uint32_t* r, uint32_t addr) {
    asm volatile("ldmatrix.sync.aligned.m8n8.x4.shared.b16 {%0,%1,%2,%3}, [%4];"
                 : "=r"(r[0]), "=r"(r[1]), "=r"(r[2]), "=r"(r[3]) : "r"(addr));
}
__device__ __forceinline__ void mma16816(float* d, const uint32_t* a, uint32_t b0, uint32_t b1) {
    asm volatile(
        "mma.sync.aligned.m16n8k16.row.col.f32.bf16.bf16.f32 "
        "{%0,%1,%2,%3}, {%4,%5,%6,%7}, {%8,%9}, {%0,%1,%2,%3};"
        : "+f"(d[0]), "+f"(d[1]), "+f"(d[2]), "+f"(d[3])
        : "r"(a[0]), "r"(a[1]), "r"(a[2]), "r"(a[3]), "r"(b0), "r"(b1));
}

// smem layout (bytes)
#define SM_A    0          // 128x128 bf16 swizzled (32KB)
#define SM_B0   32768      // 128x128 bf16 swizzled (32KB)
#define SM_B1   65536      // 128x128 bf16 swizzled (32KB)
#define SM_IL   98304      // int[512] column labels (whole quad)
#define SM_JL   100352     // int[128] row labels
#define SM_PART 100864     // float[128][4]
#define SM_TOT  102912

// ---------------- Kernel 1: normalize (4 rows/warp), f32 + bf16 -------------
__global__ void ntx_norm_kernel(const float* __restrict__ zis,
                                const float* __restrict__ zjs) {
    int warp = (blockIdx.x * blockDim.x + threadIdx.x) >> 5;
    int lane = threadIdx.x & 31;
    int sub = lane & 7;
    int rq  = lane >> 3;
    int row = warp * 4 + rq;
    if (row >= 2 * B_SZ) return;
    bool isZj = row >= B_SZ;
    int r = isZj ? row - B_SZ : row;
    const float* src = (isZj ? zjs : zis) + (size_t)r * D_SZ;
    float* d32 = (isZj ? g_zj32 : g_zi32) + (size_t)r * D_SZ;
    __nv_bfloat16* db = (isZj ? g_zjb : g_zib) + (size_t)r * D_SZ;

    float4 v[4];
#pragma unroll
    for (int q = 0; q < 4; q++) v[q] = ((const float4*)src)[sub + 8 * q];
    float ss = 0.0f;
#pragma unroll
    for (int q = 0; q < 4; q++)
        ss += v[q].x * v[q].x + v[q].y * v[q].y + v[q].z * v[q].z + v[q].w * v[q].w;
    ss += __shfl_xor_sync(0xFFFFFFFFu, ss, 1);
    ss += __shfl_xor_sync(0xFFFFFFFFu, ss, 2);
    ss += __shfl_xor_sync(0xFFFFFFFFu, ss, 4);
    float sc = rsqrtf(ss);
#pragma unroll
    for (int q = 0; q < 4; q++) {
        v[q].x *= sc; v[q].y *= sc; v[q].z *= sc; v[q].w *= sc;
        ((float4*)d32)[sub + 8 * q] = v[q];
        __nv_bfloat162 b01 = __nv_bfloat162(__float2bfloat16_rn(v[q].x), __float2bfloat16_rn(v[q].y));
        __nv_bfloat162 b23 = __nv_bfloat162(__float2bfloat16_rn(v[q].z), __float2bfloat16_rn(v[q].w));
        ((uint2*)db)[sub + 8 * q] = make_uint2(*(uint32_t*)&b01, *(uint32_t*)&b23);
    }
}

// ---------------- Kernel 2: exact f32 positive logit per row ----------------
__global__ void ntx_pos_kernel(const int* __restrict__ idxp) {
    int warp = (blockIdx.x * blockDim.x + threadIdx.x) >> 5;
    int lane = threadIdx.x & 31;
    if (warp >= B_SZ) return;
    int p = idxp[0] + warp;
    p = p < 0 ? 0 : (p > B_SZ - 1 ? B_SZ - 1 : p);
    float4 a = ((const float4*)(g_zj32 + (size_t)warp * D_SZ))[lane];
    float4 b = ((const float4*)(g_zi32 + (size_t)p * D_SZ))[lane];
    float d = a.x * b.x + a.y * b.y + a.z * b.z + a.w * b.w;
#pragma unroll
    for (int o = 16; o; o >>= 1) d += __shfl_xor_sync(0xFFFFFFFFu, d, o);
    if (lane == 0) g_pos[warp] = d * 10.0f;
}

// ---------------- Kernel 3: pipelined mma.sync + fused masked exp-sum -------
__global__ __launch_bounds__(256, 2)
void ntx_main_kernel(const long long* __restrict__ ilab,
                     const long long* __restrict__ jlab) {
    extern __shared__ char smc[];
    const uint32_t sb = smem_u32(smc);
    const int tid = threadIdx.x;
    const int w = tid >> 5;
    const int l = tid & 31;
    const int wm = w >> 2;           // 0..1
    const int wn = w & 3;            // 0..3

    const int rowBase = blockIdx.y * 128;
    const int colBase = blockIdx.x * 512;

    int* s_il = (int*)(smc + SM_IL);
    int* s_jl = (int*)(smc + SM_JL);
    float* s_part = (float*)(smc + SM_PART);

    // ---- issue A + B(0) via cp.async (swizzled dst) ----
    {
        int r = tid >> 1, c0 = (tid & 1) * 8;     // 2 threads per row, 8 chunks each
#pragma unroll
        for (int i = 0; i < 8; i++) {
            int c = c0 + i;
            cpasync16(sb + SM_A + r * 256 + ((c ^ (r & 7)) << 4),
                      g_zjb + (size_t)(rowBase + r) * D_SZ + c * 8);
        }
#pragma unroll
        for (int i = 0; i < 8; i++) {
            int c = c0 + i;
            cpasync16(sb + SM_B0 + r * 256 + ((c ^ (r & 7)) << 4),
                      g_zib + (size_t)(colBase + r) * D_SZ + c * 8);
        }
    }
    CP_COMMIT();

    // labels for the whole 512-col quad + 128 rows (regular loads)
    for (int i = tid; i < 512; i += 256) s_il[i] = (int)ilab[colBase + i];
    if (tid < 128) s_jl[tid] = (int)jlab[rowBase + tid];

    const int rA = wm * 64 + (l & 15);
    const int rB = wn * 32 + ((l >> 4) << 3) + (l & 7);
    const uint32_t aRowOff = (uint32_t)rA * 256;
    const uint32_t bRowOff = (uint32_t)rB * 256;
    const int cbA = l >> 4;
    const int cbB = (l >> 3) & 1;
    const int sw = l & 7;

    // persistent per-row exp-sums across the 4 column tiles
    float racc0[4], racc1[4];
#pragma unroll
    for (int mt = 0; mt < 4; mt++) { racc0[mt] = 0.0f; racc1[mt] = 0.0f; }
    int jl0[4], jl1[4];

    for (int t = 0; t < 4; t++) {
        const uint32_t smB = (t & 1) ? SM_B1 : SM_B0;
        CP_WAIT0();
        __syncthreads();              // B(t) visible to all; prev buffer free
        if (t == 0) {
#pragma unroll
            for (int mt = 0; mt < 4; mt++) {
                jl0[mt] = s_jl[wm * 64 + mt * 16 + (l >> 2)];
                jl1[mt] = s_jl[wm * 64 + mt * 16 + (l >> 2) + 8];
            }
        }
        // prefetch B(t+1) into the other buffer
        if (t < 3) {
            int r = tid >> 1, c0 = (tid & 1) * 8;
            uint32_t dstB = (t & 1) ? SM_B0 : SM_B1;
            const __nv_bfloat16* srcB = g_zib + (size_t)(colBase + (t + 1) * 128) * D_SZ;
#pragma unroll
            for (int i = 0; i < 8; i++) {
                int c = c0 + i;
                cpasync16(sb + dstB + r * 256 + ((c ^ (r & 7)) << 4),
                          srcB + (size_t)r * D_SZ + c * 8);
            }
            CP_COMMIT();
        }

        // ---- MMA over K=128 ----
        float acc[4][4][4];
#pragma unroll
        for (int mt = 0; mt < 4; mt++)
#pragma unroll
            for (int nt = 0; nt < 4; nt++)
#pragma unroll
                for (int e = 0; e < 4; e++) acc[mt][nt][e] = 0.0f;

#pragma unroll
        for (int k = 0; k < 8; k++) {
            uint32_t a[4][4], b[2][4];
            uint32_t chA = (uint32_t)(((2 * k + cbA) ^ sw) << 4);
            uint32_t chB = (uint32_t)(((2 * k + cbB) ^ sw) << 4);
#pragma unroll
            for (int mt = 0; mt < 4; mt++)
                ldsm4(a[mt], sb + SM_A + aRowOff + (uint32_t)(mt * 16 * 256) + chA);
#pragma unroll
            for (int np = 0; np < 2; np++)
                ldsm4(b[np], sb + smB + bRowOff + (uint32_t)(np * 16 * 256) + chB);
#pragma unroll
            for (int mt = 0; mt < 4; mt++)
#pragma unroll
                for (int nt = 0; nt < 4; nt++)
                    mma16816(acc[mt][nt], a[mt], b[nt >> 1][(nt & 1) * 2], b[nt >> 1][(nt & 1) * 2 + 1]);
        }

        // ---- epilogue: MUFU exp + mask; accumulate persistent row sums ----
        const int* ilq = s_il + t * 128;
#pragma unroll
        for (int mt = 0; mt < 4; mt++) {
#pragma unroll
            for (int nt = 0; nt < 4; nt++) {
                int cloc = wn * 32 + nt * 8 + 2 * (l & 3);
                int2 cl = *(const int2*)(ilq + cloc);
                float e00 = exp10m(acc[mt][nt][0]);
                float e01 = exp10m(acc[mt][nt][1]);
                float e10 = exp10m(acc[mt][nt][2]);
                float e11 = exp10m(acc[mt][nt][3]);
                racc0[mt] += (cl.x != jl0[mt] ? e00 : 0.0f) + (cl.y != jl0[mt] ? e01 : 0.0f);
                racc1[mt] += (cl.x != jl1[mt] ? e10 : 0.0f) + (cl.y != jl1[mt] ? e11 : 0.0f);
            }
        }
        __syncthreads();              // all warps done reading B(t) before overwrite
    }

    // ---- combine across lanes / warps, write one partial per row ----
#pragma unroll
    for (int mt = 0; mt < 4; mt++) {
        float r0 = racc0[mt], r1 = racc1[mt];
        r0 += __shfl_xor_sync(0xFFFFFFFFu, r0, 1);
        r0 += __shfl_xor_sync(0xFFFFFFFFu, r0, 2);
        r1 += __shfl_xor_sync(0xFFFFFFFFu, r1, 1);
        r1 += __shfl_xor_sync(0xFFFFFFFFu, r1, 2);
        if ((l & 3) == 0) {
            int rloc0 = wm * 64 + mt * 16 + (l >> 2);
            s_part[rloc0 * 4 + wn] = r0;
            s_part[(rloc0 + 8) * 4 + wn] = r1;
        }
    }
    __syncthreads();
    if (tid < 128) {
        float s = s_part[tid * 4] + s_part[tid * 4 + 1] + s_part[tid * 4 + 2] + s_part[tid * 4 + 3];
        g_part[(size_t)(rowBase + tid) * 16 + blockIdx.x] = s;
    }
}

// ---------------- Kernel 4a: thread-per-row loss + per-block sum ------------
__global__ void ntx_row_kernel() {
    __shared__ float r[256];
    int row = blockIdx.x * 256 + threadIdx.x;
    const float4* p = (const float4*)(g_part + (size_t)row * 16);
    float4 a = p[0], b = p[1], c = p[2], d = p[3];
    float s = (a.x + a.y + a.z + a.w) + (b.x + b.y + b.z + b.w)
            + (c.x + c.y + c.z + c.w) + (d.x + d.y + d.z + d.w);
    float pos = g_pos[row];
    float ep;
    asm("ex2.approx.f32 %0, %1;" : "=f"(ep) : "f"(pos * 1.4426950408889634f));
    r[threadIdx.x] = logf(s + ep) - pos;
    __syncthreads();
    for (int o = 128; o; o >>= 1) {
        if (threadIdx.x < o) r[threadIdx.x] += r[threadIdx.x + o];
        __syncthreads();
    }
    if (threadIdx.x == 0) g_blocksum[blockIdx.x] = r[0];
}

// ---------------- Kernel 4b: deterministic final ----------------------------
__global__ void ntx_fin_kernel(float* __restrict__ out) {
    if (threadIdx.x == 0) {
        float s = 0.0f;
#pragma unroll
        for (int i = 0; i < 32; i++) s += g_blocksum[i];
        out[0] = s / (float)B_SZ;
    }
}

extern "C" void kernel_launch(void* const* d_in, const int* in_sizes, int n_in,
                              void* d_out, int out_size) {
    const float* zis = (const float*)d_in[0];
    const float* zjs = (const float*)d_in[1];
    const long long* ilab = (const long long*)d_in[2];
    const long long* jlab = (const long long*)d_in[3];
    // d_in[4] = weights: (loss*w)/w cancels, unused
    const int* idxp = (const int*)d_in[5];
    float* out = (float*)d_out;

    cudaFuncSetAttribute(ntx_main_kernel,
                         cudaFuncAttributeMaxDynamicSharedMemorySize, SM_TOT);

    ntx_norm_kernel<<<512, 256>>>(zis, zjs);
    ntx_pos_kernel<<<1024, 256>>>(idxp);
    dim3 grid(16, 64);
    ntx_main_kernel<<<grid, 256, SM_TOT>>>(ilab, jlab);
    ntx_row_kernel<<<32, 256>>>();
    ntx_fin_kernel<<<1, 32>>>(out);
}

// round 6
// speedup vs baseline: 1.1225x; 1.1225x over previous
#include <cuda_runtime.h>
#include <cuda_bf16.h>
#include <math.h>
#include <stdint.h>

// NTXentLoss: normalize -> (zj @ zi^T)/T -> per-row masked sum(exp) -> log - pos -> mean
// B=8192, D=128, T=0.1. mma.sync bf16 (M-split, 3 CTAs/SM) + MUFU.EX2 epilogue.

#define B_SZ 8192
#define D_SZ 128

__device__ float         g_zi32[B_SZ * D_SZ];
__device__ float         g_zj32[B_SZ * D_SZ];
__device__ __nv_bfloat16 g_zib[B_SZ * D_SZ];
__device__ __nv_bfloat16 g_zjb[B_SZ * D_SZ];
__device__ float         g_pos[B_SZ];
__device__ float         g_part[B_SZ * 64];   // [row][colBlock]
__device__ float         g_blocksum[128];

#define EXP_C1 14.42695040888963f             // 10 * log2(e)

__device__ __forceinline__ float exp10m(float a) {
    float t = a * EXP_C1;
    float r;
    asm("ex2.approx.f32 %0, %1;" : "=f"(r) : "f"(t));
    return r;
}
__device__ __forceinline__ uint32_t smem_u32(const void* p) {
    uint32_t a;
    asm("{ .reg .u64 t; cvta.to.shared.u64 t, %1; cvt.u32.u64 %0, t; }" : "=r"(a) : "l"(p));
    return a;
}
__device__ __forceinline__ void ldsm4(uint32_t* r, uint32_t addr) {
    asm volatile("ldmatrix.sync.aligned.m8n8.x4.shared.b16 {%0,%1,%2,%3}, [%4];"
                 : "=r"(r[0]), "=r"(r[1]), "=r"(r[2]), "=r"(r[3]) : "r"(addr));
}
__device__ __forceinline__ void mma16816(float* d, const uint32_t* a, uint32_t b0, uint32_t b1) {
    asm volatile(
        "mma.sync.aligned.m16n8k16.row.col.f32.bf16.bf16.f32 "
        "{%0,%1,%2,%3}, {%4,%5,%6,%7}, {%8,%9}, {%0,%1,%2,%3};"
        : "+f"(d[0]), "+f"(d[1]), "+f"(d[2]), "+f"(d[3])
        : "r"(a[0]), "r"(a[1]), "r"(a[2]), "r"(a[3]), "r"(b0), "r"(b1));
}

// smem layout (bytes)
#define SM_A    0          // 128x128 bf16 swizzled (32KB)
#define SM_B    32768      // 128x128 bf16 swizzled (32KB)
#define SM_IL   65536      // int[128]
#define SM_JL   66048      // int[128]
#define SM_PART 66560      // float[128][4]
#define SM_TOT  68608

// ---------------- dummy kernels (shift ncu -s 5 -c 1 onto the main kernel) --
__global__ void ntx_dummy_kernel() {}

// ---------------- Kernel 1: normalize (4 rows/warp), f32 + bf16 -------------
__global__ void ntx_norm_kernel(const float* __restrict__ zis,
                                const float* __restrict__ zjs) {
    int warp = (blockIdx.x * blockDim.x + threadIdx.x) >> 5;
    int lane = threadIdx.x & 31;
    int sub = lane & 7;
    int rq  = lane >> 3;
    int row = warp * 4 + rq;
    if (row >= 2 * B_SZ) return;
    bool isZj = row >= B_SZ;
    int r = isZj ? row - B_SZ : row;
    const float* src = (isZj ? zjs : zis) + (size_t)r * D_SZ;
    float* d32 = (isZj ? g_zj32 : g_zi32) + (size_t)r * D_SZ;
    __nv_bfloat16* db = (isZj ? g_zjb : g_zib) + (size_t)r * D_SZ;

    float4 v[4];
#pragma unroll
    for (int q = 0; q < 4; q++) v[q] = ((const float4*)src)[sub + 8 * q];
    float ss = 0.0f;
#pragma unroll
    for (int q = 0; q < 4; q++)
        ss += v[q].x * v[q].x + v[q].y * v[q].y + v[q].z * v[q].z + v[q].w * v[q].w;
    ss += __shfl_xor_sync(0xFFFFFFFFu, ss, 1);
    ss += __shfl_xor_sync(0xFFFFFFFFu, ss, 2);
    ss += __shfl_xor_sync(0xFFFFFFFFu, ss, 4);
    float sc = rsqrtf(ss);
#pragma unroll
    for (int q = 0; q < 4; q++) {
        v[q].x *= sc; v[q].y *= sc; v[q].z *= sc; v[q].w *= sc;
        ((float4*)d32)[sub + 8 * q] = v[q];
        __nv_bfloat162 b01 = __nv_bfloat162(__float2bfloat16_rn(v[q].x), __float2bfloat16_rn(v[q].y));
        __nv_bfloat162 b23 = __nv_bfloat162(__float2bfloat16_rn(v[q].z), __float2bfloat16_rn(v[q].w));
        ((uint2*)db)[sub + 8 * q] = make_uint2(*(uint32_t*)&b01, *(uint32_t*)&b23);
    }
}

// ---------------- Kernel 2: exact f32 positive logit per row ----------------
__global__ void ntx_pos_kernel(const int* __restrict__ idxp) {
    int warp = (blockIdx.x * blockDim.x + threadIdx.x) >> 5;
    int lane = threadIdx.x & 31;
    if (warp >= B_SZ) return;
    int p = idxp[0] + warp;
    p = p < 0 ? 0 : (p > B_SZ - 1 ? B_SZ - 1 : p);
    float4 a = ((const float4*)(g_zj32 + (size_t)warp * D_SZ))[lane];
    float4 b = ((const float4*)(g_zi32 + (size_t)p * D_SZ))[lane];
    float d = a.x * b.x + a.y * b.y + a.z * b.z + a.w * b.w;
#pragma unroll
    for (int o = 16; o; o >>= 1) d += __shfl_xor_sync(0xFFFFFFFFu, d, o);
    if (lane == 0) g_pos[warp] = d * 10.0f;
}

// ---------------- Kernel 3: mma.sync GEMM (M-split) + fused exp-sum ---------
__global__ __launch_bounds__(256, 3)
void ntx_main_kernel(const long long* __restrict__ ilab,
                     const long long* __restrict__ jlab) {
    extern __shared__ char smc[];
    const uint32_t sb = smem_u32(smc);
    const int tid = threadIdx.x;
    const int w = tid >> 5;
    const int l = tid & 31;
    const int wm = w >> 2;           // 0..1 (row band of 64)
    const int wn = w & 3;            // 0..3 (col band of 32)

    const int rowBase = blockIdx.y * 128;
    const int colBase = blockIdx.x * 128;

    int* s_il = (int*)(smc + SM_IL);
    int* s_jl = (int*)(smc + SM_JL);
    float* s_part = (float*)(smc + SM_PART);

    // ---- load tiles (xor-swizzled: chunk c of row r stored at c^(r&7)) ----
#pragma unroll
    for (int i = 0; i < 8; i++) {
        int idx = tid + i * 256;
        int r = idx >> 4, c = idx & 15;
        uint4 v = *(const uint4*)(g_zjb + (size_t)(rowBase + r) * D_SZ + c * 8);
        *(uint4*)(smc + SM_A + r * 256 + ((c ^ (r & 7)) << 4)) = v;
    }
#pragma unroll
    for (int i = 0; i < 8; i++) {
        int idx = tid + i * 256;
        int r = idx >> 4, c = idx & 15;
        uint4 v = *(const uint4*)(g_zib + (size_t)(colBase + r) * D_SZ + c * 8);
        *(uint4*)(smc + SM_B + r * 256 + ((c ^ (r & 7)) << 4)) = v;
    }
    if (tid < 128) s_il[tid] = (int)ilab[colBase + tid];
    else           s_jl[tid - 128] = (int)jlab[rowBase + tid - 128];
    __syncthreads();

    const int rA = wm * 64 + (l & 15);
    const int rB = wn * 32 + ((l >> 4) << 3) + (l & 7);
    const uint32_t aRowOff = (uint32_t)rA * 256;
    const uint32_t bRowOff = (uint32_t)rB * 256;
    const int cbA = l >> 4;
    const int cbB = (l >> 3) & 1;
    const int sw = l & 7;

    // ---- two M-halves: 32 acc regs each, epilogue per half ----
#pragma unroll
    for (int half = 0; half < 2; half++) {
        float acc[2][4][4];
#pragma unroll
        for (int mt = 0; mt < 2; mt++)
#pragma unroll
            for (int nt = 0; nt < 4; nt++)
#pragma unroll
                for (int e = 0; e < 4; e++) acc[mt][nt][e] = 0.0f;

#pragma unroll
        for (int k = 0; k < 8; k++) {
            uint32_t a[2][4], b[2][4];
            uint32_t chA = (uint32_t)(((2 * k + cbA) ^ sw) << 4);
            uint32_t chB = (uint32_t)(((2 * k + cbB) ^ sw) << 4);
#pragma unroll
            for (int mt = 0; mt < 2; mt++)
                ldsm4(a[mt], sb + SM_A + aRowOff + (uint32_t)((half * 2 + mt) * 16 * 256) + chA);
#pragma unroll
            for (int np = 0; np < 2; np++)
                ldsm4(b[np], sb + SM_B + bRowOff + (uint32_t)(np * 16 * 256) + chB);
#pragma unroll
            for (int mt = 0; mt < 2; mt++)
#pragma unroll
                for (int nt = 0; nt < 4; nt++)
                    mma16816(acc[mt][nt], a[mt], b[nt >> 1][(nt & 1) * 2], b[nt >> 1][(nt & 1) * 2 + 1]);
        }

        // epilogue: MUFU exp + mask + per-row accumulation
#pragma unroll
        for (int mt = 0; mt < 2; mt++) {
            int rloc0 = wm * 64 + (half * 2 + mt) * 16 + (l >> 2);
            int rloc1 = rloc0 + 8;
            int jl0 = s_jl[rloc0];
            int jl1 = s_jl[rloc1];
            float racc0 = 0.0f, racc1 = 0.0f;
#pragma unroll
            for (int nt = 0; nt < 4; nt++) {
                int cloc = wn * 32 + nt * 8 + 2 * (l & 3);
                int2 cl = *(const int2*)(s_il + cloc);
                float e00 = exp10m(acc[mt][nt][0]);
                float e01 = exp10m(acc[mt][nt][1]);
                float e10 = exp10m(acc[mt][nt][2]);
                float e11 = exp10m(acc[mt][nt][3]);
                racc0 += (cl.x != jl0 ? e00 : 0.0f) + (cl.y != jl0 ? e01 : 0.0f);
                racc1 += (cl.x != jl1 ? e10 : 0.0f) + (cl.y != jl1 ? e11 : 0.0f);
            }
            racc0 += __shfl_xor_sync(0xFFFFFFFFu, racc0, 1);
            racc0 += __shfl_xor_sync(0xFFFFFFFFu, racc0, 2);
            racc1 += __shfl_xor_sync(0xFFFFFFFFu, racc1, 1);
            racc1 += __shfl_xor_sync(0xFFFFFFFFu, racc1, 2);
            if ((l & 3) == 0) {
                s_part[rloc0 * 4 + wn] = racc0;
                s_part[rloc1 * 4 + wn] = racc1;
            }
        }
    }
    __syncthreads();

    if (tid < 128) {
        float s = s_part[tid * 4] + s_part[tid * 4 + 1] + s_part[tid * 4 + 2] + s_part[tid * 4 + 3];
        g_part[(size_t)(rowBase + tid) * 64 + blockIdx.x] = s;
    }
}

// ---------------- Kernel 4a: thread-per-row loss + per-block sum ------------
__global__ void ntx_row_kernel() {
    __shared__ float r[64];
    int row = blockIdx.x * 64 + threadIdx.x;
    const float4* p = (const float4*)(g_part + (size_t)row * 64);
    float s = 0.0f;
#pragma unroll
    for (int q = 0; q < 16; q++) {
        float4 v = p[q];
        s += (v.x + v.y) + (v.z + v.w);
    }
    float pos = g_pos[row];
    float ep;
    asm("ex2.approx.f32 %0, %1;" : "=f"(ep) : "f"(pos * 1.4426950408889634f));
    r[threadIdx.x] = logf(s + ep) - pos;
    __syncthreads();
    for (int o = 32; o; o >>= 1) {
        if (threadIdx.x < o) r[threadIdx.x] += r[threadIdx.x + o];
        __syncthreads();
    }
    if (threadIdx.x == 0) g_blocksum[blockIdx.x] = r[0];
}

// ---------------- Kernel 4b: deterministic final ----------------------------
__global__ void ntx_fin_kernel(float* __restrict__ out) {
    if (threadIdx.x == 0) {
        float s = 0.0f;
#pragma unroll
        for (int i = 0; i < 128; i++) s += g_blocksum[i];
        out[0] = s / (float)B_SZ;
    }
}

extern "C" void kernel_launch(void* const* d_in, const int* in_sizes, int n_in,
                              void* d_out, int out_size) {
    const float* zis = (const float*)d_in[0];
    const float* zjs = (const float*)d_in[1];
    const long long* ilab = (const long long*)d_in[2];
    const long long* jlab = (const long long*)d_in[3];
    // d_in[4] = weights: (loss*w)/w cancels, unused
    const int* idxp = (const int*)d_in[5];
    float* out = (float*)d_out;

    cudaFuncSetAttribute(ntx_main_kernel,
                         cudaFuncAttributeMaxDynamicSharedMemorySize, SM_TOT);

    // 3 dummies so ncu (-s 5 -c 1) captures ntx_main_kernel as launch #6
    ntx_dummy_kernel<<<1, 32>>>();
    ntx_dummy_kernel<<<1, 32>>>();
    ntx_dummy_kernel<<<1, 32>>>();
    ntx_norm_kernel<<<512, 256>>>(zis, zjs);
    ntx_pos_kernel<<<1024, 256>>>(idxp);
    dim3 grid(64, 64);
    ntx_main_kernel<<<grid, 256, SM_TOT>>>(ilab, jlab);
    ntx_row_kernel<<<128, 64>>>();
    ntx_fin_kernel<<<1, 32>>>(out);
}

// round 7
// speedup vs baseline: 1.1421x; 1.0175x over previous
#include <cuda_runtime.h>
#include <cuda_bf16.h>
#include <math.h>
#include <stdint.h>

// NTXentLoss: normalize -> (zj @ zi^T)/T -> per-row masked sum(exp) -> log - pos -> mean
// B=8192, D=128, T=0.1. FP8 e4m3 mma.sync (m16n8k32) + MUFU.EX2 epilogue; pos exact f32.

#define B_SZ 8192
#define D_SZ 128

__device__ float   g_zi32[B_SZ * D_SZ];
__device__ float   g_zj32[B_SZ * D_SZ];
__device__ uint8_t g_zi8[B_SZ * D_SZ];
__device__ uint8_t g_zj8[B_SZ * D_SZ];
__device__ float   g_pos[B_SZ];
__device__ float   g_part[B_SZ * 64];   // [row][colBlock]
__device__ float   g_blocksum[128];

#define EXP_C1 14.42695040888963f       // 10 * log2(e)

__device__ __forceinline__ float exp10m(float a) {
    float t = a * EXP_C1;
    float r;
    asm("ex2.approx.f32 %0, %1;" : "=f"(r) : "f"(t));
    return r;
}
__device__ __forceinline__ uint32_t smem_u32(const void* p) {
    uint32_t a;
    asm("{ .reg .u64 t; cvta.to.shared.u64 t, %1; cvt.u32.u64 %0, t; }" : "=r"(a) : "l"(p));
    return a;
}
// pack 4 floats -> 4 e4m3 bytes (byte0=x0 .. byte3=x3)
__device__ __forceinline__ uint32_t pack_e4m3x4(float x0, float x1, float x2, float x3) {
    uint16_t lo, hi;
    asm("cvt.rn.satfinite.e4m3x2.f32 %0, %1, %2;" : "=h"(lo) : "f"(x1), "f"(x0));
    asm("cvt.rn.satfinite.e4m3x2.f32 %0, %1, %2;" : "=h"(hi) : "f"(x3), "f"(x2));
    return (uint32_t)lo | ((uint32_t)hi << 16);
}
__device__ __forceinline__ void ldsm4(uint32_t* r, uint32_t addr) {
    asm volatile("ldmatrix.sync.aligned.m8n8.x4.shared.b16 {%0,%1,%2,%3}, [%4];"
                 : "=r"(r[0]), "=r"(r[1]), "=r"(r[2]), "=r"(r[3]) : "r"(addr));
}
__device__ __forceinline__ void mma_fp8(float* d, const uint32_t* a, uint32_t b0, uint32_t b1) {
    asm volatile(
        "mma.sync.aligned.m16n8k32.row.col.f32.e4m3.e4m3.f32 "
        "{%0,%1,%2,%3}, {%4,%5,%6,%7}, {%8,%9}, {%0,%1,%2,%3};"
        : "+f"(d[0]), "+f"(d[1]), "+f"(d[2]), "+f"(d[3])
        : "r"(a[0]), "r"(a[1]), "r"(a[2]), "r"(a[3]), "r"(b0), "r"(b1));
}

// smem layout (bytes): fp8 tiles are 128 rows x 128B, xor-swizzled (8 chunks/row)
#define SM_A    0          // 16KB
#define SM_B    16384      // 16KB
#define SM_IL   32768      // int[128]
#define SM_JL   33280      // int[128]
#define SM_PART 33792      // float[128][4]
#define SM_TOT  35840

__global__ void ntx_dummy_kernel() {}

// ---------------- Kernel 1: normalize -> f32 + fp8(e4m3) copies -------------
__global__ void ntx_norm_kernel(const float* __restrict__ zis,
                                const float* __restrict__ zjs) {
    int warp = (blockIdx.x * blockDim.x + threadIdx.x) >> 5;
    int lane = threadIdx.x & 31;
    int sub = lane & 7;
    int rq  = lane >> 3;
    int row = warp * 4 + rq;
    if (row >= 2 * B_SZ) return;
    bool isZj = row >= B_SZ;
    int r = isZj ? row - B_SZ : row;
    const float* src = (isZj ? zjs : zis) + (size_t)r * D_SZ;
    float* d32 = (isZj ? g_zj32 : g_zi32) + (size_t)r * D_SZ;
    uint8_t* d8 = (isZj ? g_zj8 : g_zi8) + (size_t)r * D_SZ;

    float4 v[4];
#pragma unroll
    for (int q = 0; q < 4; q++) v[q] = ((const float4*)src)[sub + 8 * q];
    float ss = 0.0f;
#pragma unroll
    for (int q = 0; q < 4; q++)
        ss += v[q].x * v[q].x + v[q].y * v[q].y + v[q].z * v[q].z + v[q].w * v[q].w;
    ss += __shfl_xor_sync(0xFFFFFFFFu, ss, 1);
    ss += __shfl_xor_sync(0xFFFFFFFFu, ss, 2);
    ss += __shfl_xor_sync(0xFFFFFFFFu, ss, 4);
    float sc = rsqrtf(ss);
    uint4 p8;
    uint32_t* pw = (uint32_t*)&p8;
#pragma unroll
    for (int q = 0; q < 4; q++) {
        v[q].x *= sc; v[q].y *= sc; v[q].z *= sc; v[q].w *= sc;
        ((float4*)d32)[sub + 8 * q] = v[q];
        pw[q] = pack_e4m3x4(v[q].x, v[q].y, v[q].z, v[q].w);
    }
    ((uint4*)d8)[sub] = p8;   // 16 contiguous fp8 bytes at chunk 'sub' ... wait
}

// NOTE on fp8 store layout: each lane owns 16 scattered floats (stride-8 float4s),
// which would NOT be 16 contiguous fp8 bytes. Use a corrected variant instead:
__global__ void ntx_norm_kernel_fix(const float* __restrict__ zis,
                                    const float* __restrict__ zjs) {
    int warp = (blockIdx.x * blockDim.x + threadIdx.x) >> 5;
    int lane = threadIdx.x & 31;
    int sub = lane & 7;            // 8 lanes per row; lane handles floats [16*sub, 16*sub+16)
    int rq  = lane >> 3;
    int row = warp * 4 + rq;
    if (row >= 2 * B_SZ) return;
    bool isZj = row >= B_SZ;
    int r = isZj ? row - B_SZ : row;
    const float* src = (isZj ? zjs : zis) + (size_t)r * D_SZ;
    float* d32 = (isZj ? g_zj32 : g_zi32) + (size_t)r * D_SZ;
    uint8_t* d8 = (isZj ? g_zj8 : g_zi8) + (size_t)r * D_SZ;

    float4 v[4];
#pragma unroll
    for (int q = 0; q < 4; q++) v[q] = ((const float4*)src)[sub * 4 + q];  // contiguous 16
    float ss = 0.0f;
#pragma unroll
    for (int q = 0; q < 4; q++)
        ss += v[q].x * v[q].x + v[q].y * v[q].y + v[q].z * v[q].z + v[q].w * v[q].w;
    ss += __shfl_xor_sync(0xFFFFFFFFu, ss, 1);
    ss += __shfl_xor_sync(0xFFFFFFFFu, ss, 2);
    ss += __shfl_xor_sync(0xFFFFFFFFu, ss, 4);
    float sc = rsqrtf(ss);
    uint4 p8;
    uint32_t* pw = (uint32_t*)&p8;
#pragma unroll
    for (int q = 0; q < 4; q++) {
        v[q].x *= sc; v[q].y *= sc; v[q].z *= sc; v[q].w *= sc;
        ((float4*)d32)[sub * 4 + q] = v[q];
        pw[q] = pack_e4m3x4(v[q].x, v[q].y, v[q].z, v[q].w);
    }
    ((uint4*)d8)[sub] = p8;    // bytes [16*sub, 16*sub+16) -- matches owned floats
}

// ---------------- Kernel 2: exact f32 positive logit per row ----------------
__global__ void ntx_pos_kernel(const int* __restrict__ idxp) {
    int warp = (blockIdx.x * blockDim.x + threadIdx.x) >> 5;
    int lane = threadIdx.x & 31;
    if (warp >= B_SZ) return;
    int p = idxp[0] + warp;
    p = p < 0 ? 0 : (p > B_SZ - 1 ? B_SZ - 1 : p);
    float4 a = ((const float4*)(g_zj32 + (size_t)warp * D_SZ))[lane];
    float4 b = ((const float4*)(g_zi32 + (size_t)p * D_SZ))[lane];
    float d = a.x * b.x + a.y * b.y + a.z * b.z + a.w * b.w;
#pragma unroll
    for (int o = 16; o; o >>= 1) d += __shfl_xor_sync(0xFFFFFFFFu, d, o);
    if (lane == 0) g_pos[warp] = d * 10.0f;
}

// ---------------- Kernel 3: FP8 mma.sync GEMM + fused masked exp-sum --------
__global__ __launch_bounds__(256, 2)
void ntx_main_kernel(const long long* __restrict__ ilab,
                     const long long* __restrict__ jlab) {
    extern __shared__ char smc[];
    const uint32_t sb = smem_u32(smc);
    const int tid = threadIdx.x;
    const int w = tid >> 5;
    const int l = tid & 31;
    const int wm = w >> 2;           // 0..1 (row band of 64)
    const int wn = w & 3;            // 0..3 (col band of 32)

    const int rowBase = blockIdx.y * 128;
    const int colBase = blockIdx.x * 128;

    int* s_il = (int*)(smc + SM_IL);
    int* s_jl = (int*)(smc + SM_JL);
    float* s_part = (float*)(smc + SM_PART);

    // ---- load fp8 tiles (xor swizzle: chunk c of row r at c^(r&7), 8 chunks/row)
#pragma unroll
    for (int i = 0; i < 4; i++) {
        int idx = tid + i * 256;                 // 0..1023
        int r = idx >> 3, c = idx & 7;
        uint4 v = *(const uint4*)(g_zj8 + (size_t)(rowBase + r) * D_SZ + c * 16);
        *(uint4*)(smc + SM_A + r * 128 + ((c ^ (r & 7)) << 4)) = v;
    }
#pragma unroll
    for (int i = 0; i < 4; i++) {
        int idx = tid + i * 256;
        int r = idx >> 3, c = idx & 7;
        uint4 v = *(const uint4*)(g_zi8 + (size_t)(colBase + r) * D_SZ + c * 16);
        *(uint4*)(smc + SM_B + r * 128 + ((c ^ (r & 7)) << 4)) = v;
    }
    if (tid < 128) s_il[tid] = (int)ilab[colBase + tid];
    else           s_jl[tid - 128] = (int)jlab[rowBase + tid - 128];
    __syncthreads();

    // ---- MMA: warp tile 64x32, K=128 in 4 k32-steps ----
    float acc[4][4][4];
#pragma unroll
    for (int mt = 0; mt < 4; mt++)
#pragma unroll
        for (int nt = 0; nt < 4; nt++)
#pragma unroll
            for (int e = 0; e < 4; e++) acc[mt][nt][e] = 0.0f;

    const int rA = wm * 64 + (l & 15);
    const int rB = wn * 32 + ((l >> 4) << 3) + (l & 7);
    const uint32_t aRowOff = (uint32_t)rA * 128;
    const uint32_t bRowOff = (uint32_t)rB * 128;
    const int cbA = l >> 4;                      // chunk bit (0/1) within k-step
    const int cbB = (l >> 3) & 1;
    const int sw = l & 7;

#pragma unroll
    for (int k = 0; k < 4; k++) {
        uint32_t a[4][4], b[2][4];
        uint32_t chA = (uint32_t)(((2 * k + cbA) ^ sw) << 4);
        uint32_t chB = (uint32_t)(((2 * k + cbB) ^ sw) << 4);
#pragma unroll
        for (int mt = 0; mt < 4; mt++)
            ldsm4(a[mt], sb + SM_A + aRowOff + (uint32_t)(mt * 16 * 128) + chA);
#pragma unroll
        for (int np = 0; np < 2; np++)
            ldsm4(b[np], sb + SM_B + bRowOff + (uint32_t)(np * 16 * 128) + chB);
#pragma unroll
        for (int mt = 0; mt < 4; mt++)
#pragma unroll
            for (int nt = 0; nt < 4; nt++)
                mma_fp8(acc[mt][nt], a[mt], b[nt >> 1][(nt & 1) * 2], b[nt >> 1][(nt & 1) * 2 + 1]);
    }

    // ---- epilogue: MUFU exp + mask + per-row accumulation ----
#pragma unroll
    for (int mt = 0; mt < 4; mt++) {
        int rloc0 = wm * 64 + mt * 16 + (l >> 2);
        int rloc1 = rloc0 + 8;
        int jl0 = s_jl[rloc0];
        int jl1 = s_jl[rloc1];
        float racc0 = 0.0f, racc1 = 0.0f;
#pragma unroll
        for (int nt = 0; nt < 4; nt++) {
            int cloc = wn * 32 + nt * 8 + 2 * (l & 3);
            int2 cl = *(const int2*)(s_il + cloc);
            float e00 = exp10m(acc[mt][nt][0]);
            float e01 = exp10m(acc[mt][nt][1]);
            float e10 = exp10m(acc[mt][nt][2]);
            float e11 = exp10m(acc[mt][nt][3]);
            racc0 += (cl.x != jl0 ? e00 : 0.0f) + (cl.y != jl0 ? e01 : 0.0f);
            racc1 += (cl.x != jl1 ? e10 : 0.0f) + (cl.y != jl1 ? e11 : 0.0f);
        }
        racc0 += __shfl_xor_sync(0xFFFFFFFFu, racc0, 1);
        racc0 += __shfl_xor_sync(0xFFFFFFFFu, racc0, 2);
        racc1 += __shfl_xor_sync(0xFFFFFFFFu, racc1, 1);
        racc1 += __shfl_xor_sync(0xFFFFFFFFu, racc1, 2);
        if ((l & 3) == 0) {
            s_part[rloc0 * 4 + wn] = racc0;
            s_part[rloc1 * 4 + wn] = racc1;
        }
    }
    __syncthreads();

    if (tid < 128) {
        float s = s_part[tid * 4] + s_part[tid * 4 + 1] + s_part[tid * 4 + 2] + s_part[tid * 4 + 3];
        g_part[(size_t)(rowBase + tid) * 64 + blockIdx.x] = s;
    }
}

// ---------------- Kernel 4a: thread-per-row loss + per-block sum ------------
__global__ void ntx_row_kernel() {
    __shared__ float r[64];
    int row = blockIdx.x * 64 + threadIdx.x;
    const float4* p = (const float4*)(g_part + (size_t)row * 64);
    float s = 0.0f;
#pragma unroll
    for (int q = 0; q < 16; q++) {
        float4 v = p[q];
        s += (v.x + v.y) + (v.z + v.w);
    }
    float pos = g_pos[row];
    float ep;
    asm("ex2.approx.f32 %0, %1;" : "=f"(ep) : "f"(pos * 1.4426950408889634f));
    r[threadIdx.x] = logf(s + ep) - pos;
    __syncthreads();
    for (int o = 32; o; o >>= 1) {
        if (threadIdx.x < o) r[threadIdx.x] += r[threadIdx.x + o];
        __syncthreads();
    }
    if (threadIdx.x == 0) g_blocksum[blockIdx.x] = r[0];
}

// ---------------- Kernel 4b: deterministic final ----------------------------
__global__ void ntx_fin_kernel(float* __restrict__ out) {
    if (threadIdx.x == 0) {
        float s = 0.0f;
#pragma unroll
        for (int i = 0; i < 128; i++) s += g_blocksum[i];
        out[0] = s / (float)B_SZ;
    }
}

extern "C" void kernel_launch(void* const* d_in, const int* in_sizes, int n_in,
                              void* d_out, int out_size) {
    const float* zis = (const float*)d_in[0];
    const float* zjs = (const float*)d_in[1];
    const long long* ilab = (const long long*)d_in[2];
    const long long* jlab = (const long long*)d_in[3];
    // d_in[4] = weights: (loss*w)/w cancels, unused
    const int* idxp = (const int*)d_in[5];
    float* out = (float*)d_out;

    cudaFuncSetAttribute(ntx_main_kernel,
                         cudaFuncAttributeMaxDynamicSharedMemorySize, SM_TOT);

    // 1 dummy => ntx_main_kernel is launch #4 (observed ncu capture slot)
    ntx_dummy_kernel<<<1, 32>>>();
    ntx_norm_kernel_fix<<<512, 256>>>(zis, zjs);
    ntx_pos_kernel<<<1024, 256>>>(idxp);
    dim3 grid(64, 64);
    ntx_main_kernel<<<grid, 256, SM_TOT>>>(ilab, jlab);
    ntx_row_kernel<<<128, 64>>>();
    ntx_fin_kernel<<<1, 32>>>(out);
}

// round 8
// speedup vs baseline: 1.1714x; 1.0257x over previous
#include <cuda_runtime.h>
#include <cuda_bf16.h>
#include <math.h>
#include <stdint.h>

// NTXentLoss: normalize -> (zj @ zi^T)/T -> per-row masked sum(exp) -> log - pos -> mean
// B=8192, D=128, T=0.1. FP8 e4m3 mma.sync, per-mt acc (16 regs) for 4 CTAs/SM.
// zj fp8 pre-scaled by 10*log2(e) so epilogue exp is a bare ex2.approx.

#define B_SZ 8192
#define D_SZ 128
#define EXP_C1 14.42695040888963f       // 10 * log2(e)

__device__ float   g_zi32[B_SZ * D_SZ];
__device__ float   g_zj32[B_SZ * D_SZ];
__device__ uint8_t g_zi8[B_SZ * D_SZ];
__device__ uint8_t g_zj8[B_SZ * D_SZ];   // holds e4m3(EXP_C1 * zj_norm)
__device__ float   g_pos[B_SZ];
__device__ float   g_part[B_SZ * 64];    // [row][colBlock]
__device__ float   g_blocksum[128];

__device__ __forceinline__ float ex2f(float t) {
    float r;
    asm("ex2.approx.f32 %0, %1;" : "=f"(r) : "f"(t));
    return r;
}
__device__ __forceinline__ uint32_t smem_u32(const void* p) {
    uint32_t a;
    asm("{ .reg .u64 t; cvta.to.shared.u64 t, %1; cvt.u32.u64 %0, t; }" : "=r"(a) : "l"(p));
    return a;
}
__device__ __forceinline__ uint32_t pack_e4m3x4(float x0, float x1, float x2, float x3) {
    uint16_t lo, hi;
    asm("cvt.rn.satfinite.e4m3x2.f32 %0, %1, %2;" : "=h"(lo) : "f"(x1), "f"(x0));
    asm("cvt.rn.satfinite.e4m3x2.f32 %0, %1, %2;" : "=h"(hi) : "f"(x3), "f"(x2));
    return (uint32_t)lo | ((uint32_t)hi << 16);
}
__device__ __forceinline__ void ldsm4(uint32_t* r, uint32_t addr) {
    asm volatile("ldmatrix.sync.aligned.m8n8.x4.shared.b16 {%0,%1,%2,%3}, [%4];"
                 : "=r"(r[0]), "=r"(r[1]), "=r"(r[2]), "=r"(r[3]) : "r"(addr));
}
__device__ __forceinline__ void mma_fp8(float* d, const uint32_t* a, uint32_t b0, uint32_t b1) {
    asm volatile(
        "mma.sync.aligned.m16n8k32.row.col.f32.e4m3.e4m3.f32 "
        "{%0,%1,%2,%3}, {%4,%5,%6,%7}, {%8,%9}, {%0,%1,%2,%3};"
        : "+f"(d[0]), "+f"(d[1]), "+f"(d[2]), "+f"(d[3])
        : "r"(a[0]), "r"(a[1]), "r"(a[2]), "r"(a[3]), "r"(b0), "r"(b1));
}

// smem layout (bytes): fp8 tiles 128 rows x 128B, xor-swizzled (8 chunks/row)
#define SM_A    0          // 16KB
#define SM_B    16384      // 16KB
#define SM_IL   32768      // int[128]
#define SM_JL   33280      // int[128]
#define SM_PART 33792      // float[128][4]
#define SM_TOT  35840

__global__ void ntx_dummy_kernel() {}

// ---------------- Kernel 1: normalize -> f32 + fp8 copies -------------------
__global__ void ntx_norm_kernel(const float* __restrict__ zis,
                                const float* __restrict__ zjs) {
    int warp = (blockIdx.x * blockDim.x + threadIdx.x) >> 5;
    int lane = threadIdx.x & 31;
    int sub = lane & 7;            // lane handles floats [16*sub, 16*sub+16)
    int rq  = lane >> 3;
    int row = warp * 4 + rq;
    if (row >= 2 * B_SZ) return;
    bool isZj = row >= B_SZ;
    int r = isZj ? row - B_SZ : row;
    const float* src = (isZj ? zjs : zis) + (size_t)r * D_SZ;
    float* d32 = (isZj ? g_zj32 : g_zi32) + (size_t)r * D_SZ;
    uint8_t* d8 = (isZj ? g_zj8 : g_zi8) + (size_t)r * D_SZ;
    float q8sc = isZj ? EXP_C1 : 1.0f;   // bake 10*log2(e) into zj fp8 copy

    float4 v[4];
#pragma unroll
    for (int q = 0; q < 4; q++) v[q] = ((const float4*)src)[sub * 4 + q];
    float ss = 0.0f;
#pragma unroll
    for (int q = 0; q < 4; q++)
        ss += v[q].x * v[q].x + v[q].y * v[q].y + v[q].z * v[q].z + v[q].w * v[q].w;
    ss += __shfl_xor_sync(0xFFFFFFFFu, ss, 1);
    ss += __shfl_xor_sync(0xFFFFFFFFu, ss, 2);
    ss += __shfl_xor_sync(0xFFFFFFFFu, ss, 4);
    float sc = rsqrtf(ss);
    float sc8 = sc * q8sc;
    uint4 p8;
    uint32_t* pw = (uint32_t*)&p8;
#pragma unroll
    for (int q = 0; q < 4; q++) {
        float4 n = make_float4(v[q].x * sc, v[q].y * sc, v[q].z * sc, v[q].w * sc);
        ((float4*)d32)[sub * 4 + q] = n;
        pw[q] = pack_e4m3x4(v[q].x * sc8, v[q].y * sc8, v[q].z * sc8, v[q].w * sc8);
    }
    ((uint4*)d8)[sub] = p8;
}

// ---------------- Kernel 2: exact f32 positive logit per row ----------------
__global__ void ntx_pos_kernel(const int* __restrict__ idxp) {
    int warp = (blockIdx.x * blockDim.x + threadIdx.x) >> 5;
    int lane = threadIdx.x & 31;
    if (warp >= B_SZ) return;
    int p = idxp[0] + warp;
    p = p < 0 ? 0 : (p > B_SZ - 1 ? B_SZ - 1 : p);
    float4 a = ((const float4*)(g_zj32 + (size_t)warp * D_SZ))[lane];
    float4 b = ((const float4*)(g_zi32 + (size_t)p * D_SZ))[lane];
    float d = a.x * b.x + a.y * b.y + a.z * b.z + a.w * b.w;
#pragma unroll
    for (int o = 16; o; o >>= 1) d += __shfl_xor_sync(0xFFFFFFFFu, d, o);
    if (lane == 0) g_pos[warp] = d * 10.0f;
}

// ---------------- Kernel 3: FP8 mma.sync, per-mt acc + fused exp-sum --------
__global__ __launch_bounds__(256, 4)
void ntx_main_kernel(const long long* __restrict__ ilab,
                     const long long* __restrict__ jlab) {
    extern __shared__ char smc[];
    const uint32_t sb = smem_u32(smc);
    const int tid = threadIdx.x;
    const int w = tid >> 5;
    const int l = tid & 31;
    const int wm = w >> 2;           // 0..1 (row band of 64)
    const int wn = w & 3;            // 0..3 (col band of 32)

    const int rowBase = blockIdx.y * 128;
    const int colBase = blockIdx.x * 128;

    int* s_il = (int*)(smc + SM_IL);
    int* s_jl = (int*)(smc + SM_JL);
    float* s_part = (float*)(smc + SM_PART);

    // ---- load fp8 tiles (xor swizzle: chunk c of row r at c^(r&7)) ----
#pragma unroll
    for (int i = 0; i < 4; i++) {
        int idx = tid + i * 256;
        int r = idx >> 3, c = idx & 7;
        uint4 v = *(const uint4*)(g_zj8 + (size_t)(rowBase + r) * D_SZ + c * 16);
        *(uint4*)(smc + SM_A + r * 128 + ((c ^ (r & 7)) << 4)) = v;
    }
#pragma unroll
    for (int i = 0; i < 4; i++) {
        int idx = tid + i * 256;
        int r = idx >> 3, c = idx & 7;
        uint4 v = *(const uint4*)(g_zi8 + (size_t)(colBase + r) * D_SZ + c * 16);
        *(uint4*)(smc + SM_B + r * 128 + ((c ^ (r & 7)) << 4)) = v;
    }
    if (tid < 128) s_il[tid] = (int)ilab[colBase + tid];
    else           s_jl[tid - 128] = (int)jlab[rowBase + tid - 128];
    __syncthreads();

    const int rA = wm * 64 + (l & 15);
    const int rB = wn * 32 + ((l >> 4) << 3) + (l & 7);
    const uint32_t aRowOff = (uint32_t)rA * 128;
    const uint32_t bRowOff = (uint32_t)rB * 128;
    const int cbA = l >> 4;
    const int cbB = (l >> 3) & 1;
    const int sw = l & 7;

    // hoist column labels (same for all mt)
    int2 cl[4];
#pragma unroll
    for (int nt = 0; nt < 4; nt++)
        cl[nt] = *(const int2*)(s_il + wn * 32 + nt * 8 + 2 * (l & 3));

    // ---- per-mt: K-loop (16 acc regs), then immediate epilogue ----
#pragma unroll
    for (int mt = 0; mt < 4; mt++) {
        float acc[4][4];
#pragma unroll
        for (int nt = 0; nt < 4; nt++)
#pragma unroll
            for (int e = 0; e < 4; e++) acc[nt][e] = 0.0f;

#pragma unroll
        for (int k = 0; k < 4; k++) {
            uint32_t a[4], b[2][4];
            uint32_t chA = (uint32_t)(((2 * k + cbA) ^ sw) << 4);
            uint32_t chB = (uint32_t)(((2 * k + cbB) ^ sw) << 4);
            ldsm4(a, sb + SM_A + aRowOff + (uint32_t)(mt * 16 * 128) + chA);
            ldsm4(b[0], sb + SM_B + bRowOff + chB);
            ldsm4(b[1], sb + SM_B + bRowOff + (uint32_t)(16 * 128) + chB);
#pragma unroll
            for (int nt = 0; nt < 4; nt++)
                mma_fp8(acc[nt], a, b[nt >> 1][(nt & 1) * 2], b[nt >> 1][(nt & 1) * 2 + 1]);
        }

        // epilogue: acc is already log2(e^logit); bare ex2 + mask + row-acc
        int rloc0 = wm * 64 + mt * 16 + (l >> 2);
        int rloc1 = rloc0 + 8;
        int jl0 = s_jl[rloc0];
        int jl1 = s_jl[rloc1];
        float racc0 = 0.0f, racc1 = 0.0f;
#pragma unroll
        for (int nt = 0; nt < 4; nt++) {
            float e00 = ex2f(acc[nt][0]);
            float e01 = ex2f(acc[nt][1]);
            float e10 = ex2f(acc[nt][2]);
            float e11 = ex2f(acc[nt][3]);
            racc0 += (cl[nt].x != jl0 ? e00 : 0.0f) + (cl[nt].y != jl0 ? e01 : 0.0f);
            racc1 += (cl[nt].x != jl1 ? e10 : 0.0f) + (cl[nt].y != jl1 ? e11 : 0.0f);
        }
        racc0 += __shfl_xor_sync(0xFFFFFFFFu, racc0, 1);
        racc0 += __shfl_xor_sync(0xFFFFFFFFu, racc0, 2);
        racc1 += __shfl_xor_sync(0xFFFFFFFFu, racc1, 1);
        racc1 += __shfl_xor_sync(0xFFFFFFFFu, racc1, 2);
        if ((l & 3) == 0) {
            s_part[rloc0 * 4 + wn] = racc0;
            s_part[rloc1 * 4 + wn] = racc1;
        }
    }
    __syncthreads();

    if (tid < 128) {
        float s = s_part[tid * 4] + s_part[tid * 4 + 1] + s_part[tid * 4 + 2] + s_part[tid * 4 + 3];
        g_part[(size_t)(rowBase + tid) * 64 + blockIdx.x] = s;
    }
}

// ---------------- Kernel 4a: thread-per-row loss + per-block sum ------------
__global__ void ntx_row_kernel() {
    __shared__ float r[64];
    int row = blockIdx.x * 64 + threadIdx.x;
    const float4* p = (const float4*)(g_part + (size_t)row * 64);
    float s = 0.0f;
#pragma unroll
    for (int q = 0; q < 16; q++) {
        float4 v = p[q];
        s += (v.x + v.y) + (v.z + v.w);
    }
    float pos = g_pos[row];
    float ep = ex2f(pos * 1.4426950408889634f);
    r[threadIdx.x] = logf(s + ep) - pos;
    __syncthreads();
    for (int o = 32; o; o >>= 1) {
        if (threadIdx.x < o) r[threadIdx.x] += r[threadIdx.x + o];
        __syncthreads();
    }
    if (threadIdx.x == 0) g_blocksum[blockIdx.x] = r[0];
}

// ---------------- Kernel 4b: deterministic final ----------------------------
__global__ void ntx_fin_kernel(float* __restrict__ out) {
    if (threadIdx.x == 0) {
        float s = 0.0f;
#pragma unroll
        for (int i = 0; i < 128; i++) s += g_blocksum[i];
        out[0] = s / (float)B_SZ;
    }
}

extern "C" void kernel_launch(void* const* d_in, const int* in_sizes, int n_in,
                              void* d_out, int out_size) {
    const float* zis = (const float*)d_in[0];
    const float* zjs = (const float*)d_in[1];
    const long long* ilab = (const long long*)d_in[2];
    const long long* jlab = (const long long*)d_in[3];
    // d_in[4] = weights: (loss*w)/w cancels, unused
    const int* idxp = (const int*)d_in[5];
    float* out = (float*)d_out;

    cudaFuncSetAttribute(ntx_main_kernel,
                         cudaFuncAttributeMaxDynamicSharedMemorySize, SM_TOT);

    // 1 dummy => ntx_main_kernel is launch #4 (ncu capture slot)
    ntx_dummy_kernel<<<1, 32>>>();
    ntx_norm_kernel<<<512, 256>>>(zis, zjs);
    ntx_pos_kernel<<<1024, 256>>>(idxp);
    dim3 grid(64, 64);
    ntx_main_kernel<<<grid, 256, SM_TOT>>>(ilab, jlab);
    ntx_row_kernel<<<128, 64>>>();
    ntx_fin_kernel<<<1, 32>>>(out);
}